// round 3
// baseline (speedup 1.0000x reference)
#include <cuda_runtime.h>
#include <cstddef>

// ---------------------------------------------------------------------------
// Differentiable JPEG (quality=75) fully fused: one CTA = 64x64 pixel tile.
//   - RGB->YCbCr (x255 scale), 2x2 avgpool of Cb/Cr
//   - per 8x8 block: D = M X M^T ; deq = diff_round(D/qt)*qt ; rec = M deq M^T
//     NOTE: the reference's "inverse" einsum ('xu,bnuv,yv') is algebraically the
//     SAME transform as the forward one (M . M^T), not the true IDCT. Replicate it.
//   - upsample chroma, YCbCr->RGB, clip, /255
// Each thread processes one full 8x8 block in registers (96 blocks per tile).
// ---------------------------------------------------------------------------

#define THREADS 96

// DCT-II orthonormal matrix accessor. Function-local constexpr array: legal in
// device code, and with fully-unrolled constant indices every coefficient
// folds to an FFMA immediate (imm-form rt_SMSP=1 on sm_103a).
__device__ __forceinline__ float m8(int r, int c) {
  constexpr float M[64] = {
     0.3535533905932738f,  0.3535533905932738f,  0.3535533905932738f,  0.3535533905932738f,
     0.3535533905932738f,  0.3535533905932738f,  0.3535533905932738f,  0.3535533905932738f,
     0.4903926402016152f,  0.4157348061512726f,  0.2777851165098011f,  0.0975451610080641f,
    -0.0975451610080641f, -0.2777851165098011f, -0.4157348061512726f, -0.4903926402016152f,
     0.4619397662556434f,  0.1913417161825449f, -0.1913417161825449f, -0.4619397662556434f,
    -0.4619397662556434f, -0.1913417161825449f,  0.1913417161825449f,  0.4619397662556434f,
     0.4157348061512726f, -0.0975451610080641f, -0.4903926402016152f, -0.2777851165098011f,
     0.2777851165098011f,  0.4903926402016152f,  0.0975451610080641f, -0.4157348061512726f,
     0.3535533905932738f, -0.3535533905932738f, -0.3535533905932738f,  0.3535533905932738f,
     0.3535533905932738f, -0.3535533905932738f, -0.3535533905932738f,  0.3535533905932738f,
     0.2777851165098011f, -0.4903926402016152f,  0.0975451610080641f,  0.4157348061512726f,
    -0.4157348061512726f, -0.0975451610080641f,  0.4903926402016152f, -0.2777851165098011f,
     0.1913417161825449f, -0.4619397662556434f,  0.4619397662556434f, -0.1913417161825449f,
    -0.1913417161825449f,  0.4619397662556434f, -0.4619397662556434f,  0.1913417161825449f,
     0.0975451610080641f, -0.2777851165098011f,  0.4157348061512726f, -0.4903926402016152f,
     0.4903926402016152f, -0.4157348061512726f,  0.2777851165098011f, -0.0975451610080641f
  };
  return M[r * 8 + c];
}

__constant__ float QTY_BASE[64] = {
  16,11,10,16,24,40,51,61,
  12,12,14,19,26,58,60,55,
  14,13,16,24,40,57,69,56,
  14,17,22,29,51,87,80,62,
  18,22,37,56,68,109,103,77,
  24,35,55,64,81,104,113,92,
  49,64,78,87,103,121,120,101,
  72,92,95,98,112,100,103,99 };

__constant__ float QTC_BASE[64] = {
  17,18,24,47,99,99,99,99,
  18,21,26,66,99,99,99,99,
  24,26,56,99,99,99,99,99,
  47,66,99,99,99,99,99,99,
  99,99,99,99,99,99,99,99,
  99,99,99,99,99,99,99,99,
  99,99,99,99,99,99,99,99,
  99,99,99,99,99,99,99,99 };

__device__ __forceinline__ float diff_round(float x) {
  float r = rintf(x);           // round half to even, matches jnp.round
  float d = x - r;
  return r + d * d * d;
}

__device__ __forceinline__ float scale_qt(float q) {
  // quality = 75 -> s = 200 - 2*75 = 50. IEEE division: many entries are exact
  // .5 ties (e.g. 850/100 = 8.5) whose rounding must match the reference.
  float t = __fdiv_rn(q * 50.0f + 50.0f, 100.0f);
  float v = diff_round(t);
  return fminf(fmaxf(v, 1.0f), 255.0f);
}

// Column pass: X <- M * X, in place (per-column 8 temps).
__device__ __forceinline__ void pass_cols(float* x) {
#pragma unroll
  for (int c = 0; c < 8; c++) {
    float t[8];
#pragma unroll
    for (int k = 0; k < 8; k++) t[k] = x[k * 8 + c];
#pragma unroll
    for (int u = 0; u < 8; u++) {
      float acc = m8(u, 0) * t[0];
#pragma unroll
      for (int k = 1; k < 8; k++)
        acc = fmaf(m8(u, k), t[k], acc);
      x[u * 8 + c] = acc;
    }
  }
}

// Row pass: X <- X * M^T, in place (per-row 8 temps).
__device__ __forceinline__ void pass_rows(float* x) {
#pragma unroll
  for (int r = 0; r < 8; r++) {
    float t[8];
#pragma unroll
    for (int k = 0; k < 8; k++) t[k] = x[r * 8 + k];
#pragma unroll
    for (int v = 0; v < 8; v++) {
      float acc = m8(v, 0) * t[0];
#pragma unroll
      for (int k = 1; k < 8; k++)
        acc = fmaf(m8(v, k), t[k], acc);
      x[r * 8 + v] = acc;
    }
  }
}

// Blocked shared layout: each 8x8 block contiguous with pitch 65 floats.
// 65 mod 32 == 1 -> lane t reading (t*65 + i) hits 32 distinct banks: conflict-free.
__device__ __forceinline__ int yidx(int ly, int lx) {
  return ((ly >> 3) * 8 + (lx >> 3)) * 65 + (ly & 7) * 8 + (lx & 7);
}
__device__ __forceinline__ int cidx(int ly, int lx) {
  return ((ly >> 3) * 4 + (lx >> 3)) * 65 + (ly & 7) * 8 + (lx & 7);
}

__global__ __launch_bounds__(THREADS, 4)
void jpeg_fused_kernel(const float* __restrict__ in, float* __restrict__ out, int H, int W) {
  __shared__ float sY[64 * 65];      // 64 Y blocks
  __shared__ float sCb[16 * 65];     // 16 Cb blocks (32x32 pooled plane)
  __shared__ float sCr[16 * 65];
  __shared__ float sQT[2][64];

  const int tid = threadIdx.x;
  const int b = blockIdx.z;
  const size_t plane = (size_t)H * W;
  const float* __restrict__ Rp = in + (size_t)b * 3 * plane;
  const float* __restrict__ Gp = Rp + plane;
  const float* __restrict__ Bp = Gp + plane;
  float* __restrict__ Ro = out + (size_t)b * 3 * plane;
  float* __restrict__ Go = Ro + plane;
  float* __restrict__ Bo = Go + plane;

  const int ox = blockIdx.x * 64;
  const int oy = blockIdx.y * 64;

  if (tid < 64) {
    sQT[0][tid] = scale_qt(QTY_BASE[tid]);
    sQT[1][tid] = scale_qt(QTC_BASE[tid]);
  }

  // ---- Load phase: 2x2 quads. Compute YCbCr, pool chroma, store to shared. ----
  for (int q = tid; q < 1024; q += THREADS) {
    const int qx = q & 31, qy = q >> 5;
    const int px = ox + 2 * qx;
    const int py = oy + 2 * qy;
    const size_t o0 = (size_t)py * W + px;
    const size_t o1 = o0 + W;

    float2 r0 = *(const float2*)(Rp + o0);
    float2 r1 = *(const float2*)(Rp + o1);
    float2 g0 = *(const float2*)(Gp + o0);
    float2 g1 = *(const float2*)(Gp + o1);
    float2 b0 = *(const float2*)(Bp + o0);
    float2 b1 = *(const float2*)(Bp + o1);

    float rr[4] = { r0.x * 255.0f, r0.y * 255.0f, r1.x * 255.0f, r1.y * 255.0f };
    float gg[4] = { g0.x * 255.0f, g0.y * 255.0f, g1.x * 255.0f, g1.y * 255.0f };
    float bb[4] = { b0.x * 255.0f, b0.y * 255.0f, b1.x * 255.0f, b1.y * 255.0f };

    float cbsum = 0.0f, crsum = 0.0f;
#pragma unroll
    for (int k = 0; k < 4; k++) {
      float yv  =  0.299f    * rr[k] + 0.587f    * gg[k] + 0.114f    * bb[k];
      float cbv = -0.168736f * rr[k] - 0.331264f * gg[k] + 0.5f      * bb[k];
      float crv =  0.5f      * rr[k] - 0.418688f * gg[k] - 0.081312f * bb[k];
      cbsum += cbv; crsum += crv;
      int ly = 2 * qy + (k >> 1);
      int lx = 2 * qx + (k & 1);
      sY[yidx(ly, lx)] = yv - 128.0f;   // DCT input is (ch - 128); +/-128 on chroma cancels
    }
    sCb[cidx(qy, qx)] = cbsum * 0.25f;
    sCr[cidx(qy, qx)] = crsum * 0.25f;
  }
  __syncthreads();

  // ---- Process phase: each thread = one full 8x8 JPEG block in registers. ----
  {
    float* base;
    const float* qt;
    if (tid < 64)      { base = sY  + tid * 65;        qt = sQT[0]; }
    else if (tid < 80) { base = sCb + (tid - 64) * 65; qt = sQT[1]; }
    else               { base = sCr + (tid - 80) * 65; qt = sQT[1]; }

    float x[64];
#pragma unroll
    for (int i = 0; i < 64; i++) x[i] = base[i];

    pass_cols(x);   // M * X
    pass_rows(x);   // ... * M^T   -> D = M X M^T

#pragma unroll
    for (int i = 0; i < 64; i++) {
      float qv = qt[i];                      // warp-uniform broadcast load
      float t  = __fdiv_rn(x[i], qv);        // IEEE fp32 division (matches ref ties)
      x[i] = diff_round(t) * qv;
    }

    // Reference "inverse" einsum == the SAME transform: rec = M deq M^T.
    pass_cols(x);
    pass_rows(x);

#pragma unroll
    for (int i = 0; i < 64; i++) base[i] = x[i];
  }
  __syncthreads();

  // ---- Output phase: upsample chroma, YCbCr->RGB, clip, /255. ----
  const float inv255 = 1.0f / 255.0f;
  for (int q = tid; q < 1024; q += THREADS) {
    const int qx = q & 31, qy = q >> 5;
    const int px = ox + 2 * qx;
    const int py = oy + 2 * qy;
    const size_t o0 = (size_t)py * W + px;
    const size_t o1 = o0 + W;

    float cb = sCb[cidx(qy, qx)];
    float cr = sCr[cidx(qy, qx)];

    float2 r2[2], g2[2], b2[2];
#pragma unroll
    for (int k = 0; k < 4; k++) {
      int ly = 2 * qy + (k >> 1);
      int lx = 2 * qx + (k & 1);
      float yv = sY[yidx(ly, lx)] + 128.0f;
      float rv = yv + 1.402f * cr;
      float gv = yv - 0.344136f * cb - 0.714136f * cr;
      float bv = yv + 1.772f * cb;
      rv = fminf(fmaxf(rv, 0.0f), 255.0f) * inv255;
      gv = fminf(fmaxf(gv, 0.0f), 255.0f) * inv255;
      bv = fminf(fmaxf(bv, 0.0f), 255.0f) * inv255;
      rv = fminf(fmaxf(rv, 0.0f), 1.0f);
      gv = fminf(fmaxf(gv, 0.0f), 1.0f);
      bv = fminf(fmaxf(bv, 0.0f), 1.0f);
      float* rp = (k & 1) ? &r2[k >> 1].y : &r2[k >> 1].x;
      float* gp = (k & 1) ? &g2[k >> 1].y : &g2[k >> 1].x;
      float* bp = (k & 1) ? &b2[k >> 1].y : &b2[k >> 1].x;
      *rp = rv; *gp = gv; *bp = bv;
    }
    *(float2*)(Ro + o0) = r2[0];
    *(float2*)(Ro + o1) = r2[1];
    *(float2*)(Go + o0) = g2[0];
    *(float2*)(Go + o1) = g2[1];
    *(float2*)(Bo + o0) = b2[0];
    *(float2*)(Bo + o1) = b2[1];
  }
}

extern "C" void kernel_launch(void* const* d_in, const int* in_sizes, int n_in,
                              void* d_out, int out_size) {
  const float* img = (const float*)d_in[0];
  float* out = (float*)d_out;
  const int H = 1024, W = 1024;
  const int B = in_sizes[0] / (3 * H * W);
  dim3 grid(W / 64, H / 64, B);
  dim3 block(THREADS);
  jpeg_fused_kernel<<<grid, block>>>(img, out, H, W);
}

// round 4
// speedup vs baseline: 1.8149x; 1.8149x over previous
#include <cuda_runtime.h>
#include <cstddef>

// ---------------------------------------------------------------------------
// Differentiable JPEG (quality=75), fused, thread-per-row formulation.
// CTA = 64x64 pixel tile = 96 8x8 blocks (64 Y + 16 Cb + 16 Cr).
// 256 threads = 32 groups of 8; each group processes one block per round
// (3 rounds). The 2-D transform M X M^T is computed as g(g(X)) with
// g(A) = M A^T: thread t reads row t (contiguous), FMAs with immediate
// coefficients, writes column t. Intra-warp exchange only -> __syncwarp.
// Shared layout: block pitch 72 floats, row pitch 9 -> conflict-free.
// ---------------------------------------------------------------------------

#define THREADS 256
#define BPITCH 72
#define RPITCH 9

// DCT-II orthonormal matrix; function-local constexpr folds to FFMA immediates.
__device__ __forceinline__ float m8(int r, int c) {
  constexpr float M[64] = {
     0.3535533905932738f,  0.3535533905932738f,  0.3535533905932738f,  0.3535533905932738f,
     0.3535533905932738f,  0.3535533905932738f,  0.3535533905932738f,  0.3535533905932738f,
     0.4903926402016152f,  0.4157348061512726f,  0.2777851165098011f,  0.0975451610080641f,
    -0.0975451610080641f, -0.2777851165098011f, -0.4157348061512726f, -0.4903926402016152f,
     0.4619397662556434f,  0.1913417161825449f, -0.1913417161825449f, -0.4619397662556434f,
    -0.4619397662556434f, -0.1913417161825449f,  0.1913417161825449f,  0.4619397662556434f,
     0.4157348061512726f, -0.0975451610080641f, -0.4903926402016152f, -0.2777851165098011f,
     0.2777851165098011f,  0.4903926402016152f,  0.0975451610080641f, -0.4157348061512726f,
     0.3535533905932738f, -0.3535533905932738f, -0.3535533905932738f,  0.3535533905932738f,
     0.3535533905932738f, -0.3535533905932738f, -0.3535533905932738f,  0.3535533905932738f,
     0.2777851165098011f, -0.4903926402016152f,  0.0975451610080641f,  0.4157348061512726f,
    -0.4157348061512726f, -0.0975451610080641f,  0.4903926402016152f, -0.2777851165098011f,
     0.1913417161825449f, -0.4619397662556434f,  0.4619397662556434f, -0.1913417161825449f,
    -0.1913417161825449f,  0.4619397662556434f, -0.4619397662556434f,  0.1913417161825449f,
     0.0975451610080641f, -0.2777851165098011f,  0.4157348061512726f, -0.4903926402016152f,
     0.4903926402016152f, -0.4157348061512726f,  0.2777851165098011f, -0.0975451610080641f
  };
  return M[r * 8 + c];
}

__constant__ float QTY_BASE[64] = {
  16,11,10,16,24,40,51,61,
  12,12,14,19,26,58,60,55,
  14,13,16,24,40,57,69,56,
  14,17,22,29,51,87,80,62,
  18,22,37,56,68,109,103,77,
  24,35,55,64,81,104,113,92,
  49,64,78,87,103,121,120,101,
  72,92,95,98,112,100,103,99 };

__constant__ float QTC_BASE[64] = {
  17,18,24,47,99,99,99,99,
  18,21,26,66,99,99,99,99,
  24,26,56,99,99,99,99,99,
  47,66,99,99,99,99,99,99,
  99,99,99,99,99,99,99,99,
  99,99,99,99,99,99,99,99,
  99,99,99,99,99,99,99,99,
  99,99,99,99,99,99,99,99 };

__device__ __forceinline__ float diff_round(float x) {
  float r = rintf(x);           // round half to even, matches jnp.round
  float d = x - r;
  return r + d * d * d;
}

__device__ __forceinline__ float scale_qt(float q) {
  // quality = 75 -> s = 50. IEEE division: several entries are exact .5 ties.
  float t = __fdiv_rn(q * 50.0f + 50.0f, 100.0f);
  float v = diff_round(t);
  return fminf(fmaxf(v, 1.0f), 255.0f);
}

// g(A) = M A^T, in place. Thread t: read row t, write column t.
__device__ __forceinline__ void gop(float* __restrict__ base, int t) {
  float a[8];
#pragma unroll
  for (int k = 0; k < 8; k++) a[k] = base[t * RPITCH + k];
  __syncwarp();                 // all rows consumed before columns overwrite
#pragma unroll
  for (int u = 0; u < 8; u++) {
    float acc = m8(u, 0) * a[0];
#pragma unroll
    for (int k = 1; k < 8; k++) acc = fmaf(m8(u, k), a[k], acc);
    base[u * RPITCH + t] = acc;
  }
  __syncwarp();                 // columns visible before next pass reads rows
}

// Full per-block pipeline: D = MXM^T ; quantize ; rec = M D M^T (the
// reference's "inverse" einsum is the SAME transform, not the true IDCT).
__device__ __forceinline__ void process_block(float* __restrict__ base, int t,
                                              const float* __restrict__ qtr) {
  gop(base, t);
  gop(base, t);
  // Quantize row t (row-local: written by this thread, re-read by this thread).
#pragma unroll
  for (int k = 0; k < 8; k++) {
    float v  = base[t * RPITCH + k];
    float q  = qtr[k];
    float tt = __fdiv_rn(v, q);            // IEEE div: match ref tie behavior
    base[t * RPITCH + k] = diff_round(tt) * q;
  }
  gop(base, t);
  gop(base, t);
}

// Shared indexers (block pitch 72, row pitch 9).
__device__ __forceinline__ int yidx(int ly, int lx) {
  return ((ly >> 3) * 8 + (lx >> 3)) * BPITCH + (ly & 7) * RPITCH + (lx & 7);
}
__device__ __forceinline__ int cidx(int ly, int lx) {
  return ((ly >> 3) * 4 + (lx >> 3)) * BPITCH + (ly & 7) * RPITCH + (lx & 7);
}

__global__ __launch_bounds__(THREADS)
void jpeg_fused_kernel(const float* __restrict__ in, float* __restrict__ out, int H, int W) {
  __shared__ float sY [64 * BPITCH];   // 64 Y blocks
  __shared__ float sCb[16 * BPITCH];   // 16 Cb blocks (32x32 pooled plane)
  __shared__ float sCr[16 * BPITCH];

  const int tid = threadIdx.x;
  const int b = blockIdx.z;
  const size_t plane = (size_t)H * W;
  const float* __restrict__ Rp = in + (size_t)b * 3 * plane;
  const float* __restrict__ Gp = Rp + plane;
  const float* __restrict__ Bp = Gp + plane;
  float* __restrict__ Ro = out + (size_t)b * 3 * plane;
  float* __restrict__ Go = Ro + plane;
  float* __restrict__ Bo = Go + plane;

  const int ox = blockIdx.x * 64;
  const int oy = blockIdx.y * 64;

  // ---- Load phase: 2x2 quads. Compute YCbCr, pool chroma, store to shared. ----
#pragma unroll
  for (int q = tid; q < 1024; q += THREADS) {
    const int qx = q & 31, qy = q >> 5;
    const int px = ox + 2 * qx;
    const int py = oy + 2 * qy;
    const size_t o0 = (size_t)py * W + px;
    const size_t o1 = o0 + W;

    float2 r0 = *(const float2*)(Rp + o0);
    float2 r1 = *(const float2*)(Rp + o1);
    float2 g0 = *(const float2*)(Gp + o0);
    float2 g1 = *(const float2*)(Gp + o1);
    float2 b0 = *(const float2*)(Bp + o0);
    float2 b1 = *(const float2*)(Bp + o1);

    float rr[4] = { r0.x * 255.0f, r0.y * 255.0f, r1.x * 255.0f, r1.y * 255.0f };
    float gg[4] = { g0.x * 255.0f, g0.y * 255.0f, g1.x * 255.0f, g1.y * 255.0f };
    float bb[4] = { b0.x * 255.0f, b0.y * 255.0f, b1.x * 255.0f, b1.y * 255.0f };

    float cbsum = 0.0f, crsum = 0.0f;
#pragma unroll
    for (int k = 0; k < 4; k++) {
      float yv  =  0.299f    * rr[k] + 0.587f    * gg[k] + 0.114f    * bb[k];
      float cbv = -0.168736f * rr[k] - 0.331264f * gg[k] + 0.5f      * bb[k];
      float crv =  0.5f      * rr[k] - 0.418688f * gg[k] - 0.081312f * bb[k];
      cbsum += cbv; crsum += crv;
      int ly = 2 * qy + (k >> 1);
      int lx = 2 * qx + (k & 1);
      sY[yidx(ly, lx)] = yv - 128.0f;   // +/-128 on chroma cancels through DCT/quant
    }
    sCb[cidx(qy, qx)] = cbsum * 0.25f;
    sCr[cidx(qy, qx)] = crsum * 0.25f;
  }
  __syncthreads();

  // ---- Process phase: 32 groups of 8 threads; each group = one block/round. ----
  {
    const int t   = tid & 7;        // row within block
    const int grp = tid >> 3;       // 0..31: group id

    // Per-thread quant-table rows in registers (one-time divergent LDC, cheap).
    float qty[8], qtc[8];
#pragma unroll
    for (int k = 0; k < 8; k++) {
      qty[k] = scale_qt(QTY_BASE[t * 8 + k]);
      qtc[k] = scale_qt(QTC_BASE[t * 8 + k]);
    }

    process_block(sY + grp * BPITCH, t, qty);          // round 0: Y blocks 0..31
    process_block(sY + (32 + grp) * BPITCH, t, qty);   // round 1: Y blocks 32..63
    float* cb = (grp < 16) ? (sCb + grp * BPITCH)      // round 2: chroma
                           : (sCr + (grp - 16) * BPITCH);
    process_block(cb, t, qtc);
  }
  __syncthreads();

  // ---- Output phase: upsample chroma, YCbCr->RGB, clip, /255. ----
  const float inv255 = 1.0f / 255.0f;
#pragma unroll
  for (int q = tid; q < 1024; q += THREADS) {
    const int qx = q & 31, qy = q >> 5;
    const int px = ox + 2 * qx;
    const int py = oy + 2 * qy;
    const size_t o0 = (size_t)py * W + px;
    const size_t o1 = o0 + W;

    float cb = sCb[cidx(qy, qx)];
    float cr = sCr[cidx(qy, qx)];

    float2 r2[2], g2[2], b2[2];
#pragma unroll
    for (int k = 0; k < 4; k++) {
      int ly = 2 * qy + (k >> 1);
      int lx = 2 * qx + (k & 1);
      float yv = sY[yidx(ly, lx)] + 128.0f;
      float rv = yv + 1.402f * cr;
      float gv = yv - 0.344136f * cb - 0.714136f * cr;
      float bv = yv + 1.772f * cb;
      rv = fminf(fmaxf(rv, 0.0f), 255.0f) * inv255;
      gv = fminf(fmaxf(gv, 0.0f), 255.0f) * inv255;
      bv = fminf(fmaxf(bv, 0.0f), 255.0f) * inv255;
      rv = fminf(fmaxf(rv, 0.0f), 1.0f);
      gv = fminf(fmaxf(gv, 0.0f), 1.0f);
      bv = fminf(fmaxf(bv, 0.0f), 1.0f);
      float* rp = (k & 1) ? &r2[k >> 1].y : &r2[k >> 1].x;
      float* gp = (k & 1) ? &g2[k >> 1].y : &g2[k >> 1].x;
      float* bp = (k & 1) ? &b2[k >> 1].y : &b2[k >> 1].x;
      *rp = rv; *gp = gv; *bp = bv;
    }
    *(float2*)(Ro + o0) = r2[0];
    *(float2*)(Ro + o1) = r2[1];
    *(float2*)(Go + o0) = g2[0];
    *(float2*)(Go + o1) = g2[1];
    *(float2*)(Bo + o0) = b2[0];
    *(float2*)(Bo + o1) = b2[1];
  }
}

extern "C" void kernel_launch(void* const* d_in, const int* in_sizes, int n_in,
                              void* d_out, int out_size) {
  const float* img = (const float*)d_in[0];
  float* out = (float*)d_out;
  const int H = 1024, W = 1024;
  const int B = in_sizes[0] / (3 * H * W);
  dim3 grid(W / 64, H / 64, B);
  dim3 block(THREADS);
  jpeg_fused_kernel<<<grid, block>>>(img, out, H, W);
}

// round 5
// speedup vs baseline: 2.0990x; 1.1565x over previous
#include <cuda_runtime.h>
#include <cstddef>

// ---------------------------------------------------------------------------
// Differentiable JPEG (quality=75), fused, thread-per-row, register-heavy.
// CTA = 64x64 pixel tile = 96 8x8 blocks (64 Y + 32 chroma).
// 256 threads = 32 groups of 8; each group does one block per round (3 rounds).
// Per block: rec = M ( diff_round( (M (X M^T)) / qt ) * qt ) M^T, computed as
// 4 identical 8-pt DCT butterflies with only TWO smem transposes per block.
// (The reference's "inverse" einsum is the forward transform again.)
// Shared pitch 9/72 -> provably conflict-free row AND column access.
// ---------------------------------------------------------------------------

#define THREADS 256
#define BPITCH 72
#define RPITCH 9

__constant__ float QTY_BASE[64] = {
  16,11,10,16,24,40,51,61,
  12,12,14,19,26,58,60,55,
  14,13,16,24,40,57,69,56,
  14,17,22,29,51,87,80,62,
  18,22,37,56,68,109,103,77,
  24,35,55,64,81,104,113,92,
  49,64,78,87,103,121,120,101,
  72,92,95,98,112,100,103,99 };

__constant__ float QTC_BASE[64] = {
  17,18,24,47,99,99,99,99,
  18,21,26,66,99,99,99,99,
  24,26,56,99,99,99,99,99,
  47,66,99,99,99,99,99,99,
  99,99,99,99,99,99,99,99,
  99,99,99,99,99,99,99,99,
  99,99,99,99,99,99,99,99,
  99,99,99,99,99,99,99,99 };

__device__ __forceinline__ float diff_round(float x) {
  float r = rintf(x);           // round half to even, matches jnp.round
  float d = x - r;
  return r + d * d * d;
}

__device__ __forceinline__ float scale_qt(float q) {
  // quality=75 -> s=50. IEEE division: entries land on exact .5 ties.
  float t = __fdiv_rn(q * 50.0f + 50.0f, 100.0f);
  float v = diff_round(t);
  return fminf(fmaxf(v, 1.0f), 255.0f);
}

// out[u] = sum_k M[u,k] a[k] -- 8-pt DCT-II via even/odd butterfly (~36 ops).
__device__ __forceinline__ void dct8(const float* __restrict__ a, float* __restrict__ out) {
  const float S  = 0.3535533905932738f;
  const float A  = 0.4619397662556434f, B  = 0.1913417161825449f;
  const float c1 = 0.4903926402016152f, c3 = 0.4157348061512726f;
  const float c5 = 0.2777851165098011f, c7 = 0.0975451610080641f;
  float e0 = a[0] + a[7], e1 = a[1] + a[6], e2 = a[2] + a[5], e3 = a[3] + a[4];
  float o0 = a[0] - a[7], o1 = a[1] - a[6], o2 = a[2] - a[5], o3 = a[3] - a[4];
  float q0 = e0 + e3, q1 = e1 + e2;
  float r0 = e0 - e3, r1 = e1 - e2;
  out[0] = S * (q0 + q1);
  out[4] = S * (q0 - q1);
  out[2] = fmaf(A, r0,  B * r1);
  out[6] = fmaf(B, r0, -A * r1);
  out[1] = fmaf(c1, o0, fmaf( c3, o1, fmaf( c5, o2,  c7 * o3)));
  out[3] = fmaf(c3, o0, fmaf(-c7, o1, fmaf(-c1, o2, -c5 * o3)));
  out[5] = fmaf(c5, o0, fmaf(-c1, o1, fmaf( c7, o2,  c3 * o3)));
  out[7] = fmaf(c7, o0, fmaf(-c5, o1, fmaf( c3, o2, -c1 * o3)));
}

// Full block pipeline, thread t of an 8-thread group. Only 2 syncwarps.
// qcol[u] = qt[u][t] (this thread's quant-table column).
__device__ __forceinline__ void process_block(float* __restrict__ base, int t,
                                              const float* __restrict__ qcol) {
  // Pass 1 (row-local): W[t,:] = row t of (X M^T).
  float a[8];
#pragma unroll
  for (int k = 0; k < 8; k++) a[k] = base[t * RPITCH + k];
  float w[8]; dct8(a, w);
#pragma unroll
  for (int k = 0; k < 8; k++) base[t * RPITCH + k] = w[k];   // own row: no pre-sync
  __syncwarp();

  // Pass 2 (column-local): D[:,t] = M * W[:,t]; quantize; E[:,t] = M * deq[:,t].
  float c[8];
#pragma unroll
  for (int k = 0; k < 8; k++) c[k] = base[k * RPITCH + t];
  float d[8]; dct8(c, d);
#pragma unroll
  for (int u = 0; u < 8; u++) {
    float q  = qcol[u];
    float tt = __fdiv_rn(d[u], q);          // IEEE div: match ref tie behavior
    d[u] = diff_round(tt) * q;
  }
  float e[8]; dct8(d, e);
#pragma unroll
  for (int u = 0; u < 8; u++) base[u * RPITCH + t] = e[u];   // own column: no pre-sync
  __syncwarp();

  // Pass 3 (row-local): rec[t,:] = row t of (E M^T).
  float r[8];
#pragma unroll
  for (int k = 0; k < 8; k++) r[k] = base[t * RPITCH + k];
  float o[8]; dct8(r, o);
#pragma unroll
  for (int k = 0; k < 8; k++) base[t * RPITCH + k] = o[k];   // own row: no pre-sync
}

// Shared indexers (block pitch 72, row pitch 9).
__device__ __forceinline__ int yidx(int ly, int lx) {
  return ((ly >> 3) * 8 + (lx >> 3)) * BPITCH + (ly & 7) * RPITCH + (lx & 7);
}
__device__ __forceinline__ int cidx(int ly, int lx) {
  return ((ly >> 3) * 4 + (lx >> 3)) * BPITCH + (ly & 7) * RPITCH + (lx & 7);
}

__global__ __launch_bounds__(THREADS, 5)
void jpeg_fused_kernel(const float* __restrict__ in, float* __restrict__ out, int H, int W) {
  __shared__ float sY[64 * BPITCH];   // 64 Y blocks
  __shared__ float sC[32 * BPITCH];   // 16 Cb blocks then 16 Cr blocks

  const int tid = threadIdx.x;
  const int b = blockIdx.z;
  const size_t plane = (size_t)H * W;
  const float* __restrict__ Rp = in + (size_t)b * 3 * plane;
  const float* __restrict__ Gp = Rp + plane;
  const float* __restrict__ Bp = Gp + plane;
  float* __restrict__ Ro = out + (size_t)b * 3 * plane;
  float* __restrict__ Go = Ro + plane;
  float* __restrict__ Bo = Go + plane;

  const int ox = blockIdx.x * 64;
  const int oy = blockIdx.y * 64;

  // ---- Load phase: 4x2 pixel units (float4 x 2 rows). 512 units, 2/thread. ----
#pragma unroll
  for (int i = 0; i < 2; i++) {
    const int u = tid + i * THREADS;
    const int ux = u & 15, uy = u >> 4;          // 16 units wide, 32 tall
    const int px = ox + 4 * ux;
    const int py = oy + 2 * uy;
    const size_t o0 = (size_t)py * W + px;
    const size_t o1 = o0 + W;

    float4 r4[2] = { *(const float4*)(Rp + o0), *(const float4*)(Rp + o1) };
    float4 g4[2] = { *(const float4*)(Gp + o0), *(const float4*)(Gp + o1) };
    float4 b4[2] = { *(const float4*)(Bp + o0), *(const float4*)(Bp + o1) };

    const float* rr = (const float*)r4;
    const float* gg = (const float*)g4;
    const float* bb = (const float*)b4;

    float cbs[2] = {0.0f, 0.0f}, crs[2] = {0.0f, 0.0f};
#pragma unroll
    for (int k = 0; k < 8; k++) {               // k = row*4 + col
      const int row = k >> 2, col = k & 3;
      float rv = rr[k] * 255.0f, gv = gg[k] * 255.0f, bv = bb[k] * 255.0f;
      float yv  =  0.299f    * rv + 0.587f    * gv + 0.114f    * bv;
      float cbv = -0.168736f * rv - 0.331264f * gv + 0.5f      * bv;
      float crv =  0.5f      * rv - 0.418688f * gv - 0.081312f * bv;
      const int h = col >> 1;                   // which 2x2 within the 4x2 unit
      cbs[h] += cbv; crs[h] += crv;
      sY[yidx(2 * uy + row, 4 * ux + col)] = yv - 128.0f;  // +/-128 chroma shift cancels
    }
    sC[cidx(uy, 2 * ux)]                  = cbs[0] * 0.25f;
    sC[cidx(uy, 2 * ux + 1)]              = cbs[1] * 0.25f;
    sC[16 * BPITCH + cidx(uy, 2 * ux)]     = crs[0] * 0.25f;
    sC[16 * BPITCH + cidx(uy, 2 * ux + 1)] = crs[1] * 0.25f;
  }
  __syncthreads();

  // ---- Process phase: 32 groups of 8 threads, 3 rounds. ----
  {
    const int t   = tid & 7;
    const int grp = tid >> 3;

    float qcol[8];
#pragma unroll
    for (int k = 0; k < 8; k++) qcol[k] = scale_qt(QTY_BASE[k * 8 + t]);
    process_block(sY + grp * BPITCH, t, qcol);
    process_block(sY + (32 + grp) * BPITCH, t, qcol);
#pragma unroll
    for (int k = 0; k < 8; k++) qcol[k] = scale_qt(QTC_BASE[k * 8 + t]);
    process_block(sC + grp * BPITCH, t, qcol);   // grp 0-15 Cb, 16-31 Cr
  }
  __syncthreads();

  // ---- Output phase: 4x2 units, upsample chroma, YCbCr->RGB, clip, /255. ----
  const float inv255 = 1.0f / 255.0f;
#pragma unroll
  for (int i = 0; i < 2; i++) {
    const int u = tid + i * THREADS;
    const int ux = u & 15, uy = u >> 4;
    const int px = ox + 4 * ux;
    const int py = oy + 2 * uy;
    const size_t o0 = (size_t)py * W + px;
    const size_t o1 = o0 + W;

    float cbv[2], crv[2];
    cbv[0] = sC[cidx(uy, 2 * ux)];
    cbv[1] = sC[cidx(uy, 2 * ux + 1)];
    crv[0] = sC[16 * BPITCH + cidx(uy, 2 * ux)];
    crv[1] = sC[16 * BPITCH + cidx(uy, 2 * ux + 1)];

    float4 r4[2], g4[2], b4[2];
    float* rr = (float*)r4; float* gg = (float*)g4; float* bb = (float*)b4;
#pragma unroll
    for (int k = 0; k < 8; k++) {
      const int row = k >> 2, col = k & 3;
      const int h = col >> 1;
      float yv = sY[yidx(2 * uy + row, 4 * ux + col)] + 128.0f;
      float cb = cbv[h], cr = crv[h];
      float rv = yv + 1.402f * cr;
      float gv = yv - 0.344136f * cb - 0.714136f * cr;
      float bv = yv + 1.772f * cb;
      rv = fminf(fmaxf(rv, 0.0f), 255.0f) * inv255;
      gv = fminf(fmaxf(gv, 0.0f), 255.0f) * inv255;
      bv = fminf(fmaxf(bv, 0.0f), 255.0f) * inv255;
      rr[k] = fminf(fmaxf(rv, 0.0f), 1.0f);
      gg[k] = fminf(fmaxf(gv, 0.0f), 1.0f);
      bb[k] = fminf(fmaxf(bv, 0.0f), 1.0f);
    }
    *(float4*)(Ro + o0) = r4[0];
    *(float4*)(Ro + o1) = r4[1];
    *(float4*)(Go + o0) = g4[0];
    *(float4*)(Go + o1) = g4[1];
    *(float4*)(Bo + o0) = b4[0];
    *(float4*)(Bo + o1) = b4[1];
  }
}

extern "C" void kernel_launch(void* const* d_in, const int* in_sizes, int n_in,
                              void* d_out, int out_size) {
  const float* img = (const float*)d_in[0];
  float* out = (float*)d_out;
  const int H = 1024, W = 1024;
  const int B = in_sizes[0] / (3 * H * W);
  dim3 grid(W / 64, H / 64, B);
  dim3 block(THREADS);
  jpeg_fused_kernel<<<grid, block>>>(img, out, H, W);
}